// round 2
// baseline (speedup 1.0000x reference)
#include <cuda_runtime.h>
#include <math.h>

#define NN 20000
#define NE 320000
#define PI_D 3.14159265358979323846

enum { M_NONE=0, M_SILU=1, M_ENV=2, M_RESID=3 };

// ---------------- scratch (static device globals; no allocation) -------------
__device__ float g_basis[16];          // BMU[8], BSIG[8]
__device__ float g_wfo[128];           // fused w_f @ w_out / 128
__device__ float g_feat[NE*40];
__device__ float g_x  [NE*128];
__device__ float g_t1 [NE*128];
__device__ float g_t2 [NE*128];
__device__ float g_env[NE];
__device__ float g_Y  [NE*9];
__device__ float g_V0 [NE*32];
__device__ float g_V1a[NE*96];
__device__ float g_V1b[NE*96];
__device__ float g_s  [NE*64];
__device__ float g_w2 [NE*32];
__device__ float g_agg[NN*288];
// CSR for deterministic-structure aggregation (built per launch)
__device__ int   g_deg[NN];
__device__ int   g_off[NN+1];
__device__ int   g_cur[NN];
__device__ int   g_eid[NE];

// ---------------- basis constants via trapz (matches numpy) ------------------
// One warp per k; lanes stride over the 1000 sample points in double precision.
__global__ void k_init() {
    int k    = threadIdx.x >> 5;      // 0..7
    int lane = threadIdx.x & 31;
    double kk = (double)(k + 1);
    double h  = (1.0 - 1e-9) / 999.0;

    // pass 1: sum of b_i
    double s = 0.0;
    for (int i = lane; i < 1000; i += 32) {
        double r = 1e-9 + h * (double)i;
        s += sqrt(2.0) * sin(PI_D * kk * r) / r;
    }
    #pragma unroll
    for (int off = 16; off; off >>= 1) s += __shfl_xor_sync(0xffffffffu, s, off);
    // endpoints
    double r0 = 1e-9, r9 = 1e-9 + h * 999.0;
    double b0 = sqrt(2.0) * sin(PI_D * kk * r0) / r0;
    double b9 = sqrt(2.0) * sin(PI_D * kk * r9) / r9;
    double mu = h * (s - 0.5 * (b0 + b9));

    // pass 2: sum of (b_i - mu)^2
    double q = 0.0;
    for (int i = lane; i < 1000; i += 32) {
        double r = 1e-9 + h * (double)i;
        double b = sqrt(2.0) * sin(PI_D * kk * r) / r;
        double dd = b - mu;
        q += dd * dd;
    }
    #pragma unroll
    for (int off = 16; off; off >>= 1) q += __shfl_xor_sync(0xffffffffu, q, off);
    double q0 = (b0 - mu) * (b0 - mu), q9 = (b9 - mu) * (b9 - mu);
    double s2 = h * (q - 0.5 * (q0 + q9));

    if (lane == 0) {
        g_basis[k]     = (float)mu;
        g_basis[8 + k] = (float)sqrt(s2);
    }
}

// ---------------- fuse w_f @ w_out -> 128 vector ------------------------------
__global__ void k_wfo(const float* __restrict__ wf, const float* __restrict__ wout) {
    int k = threadIdx.x;
    float s = 0.f;
    for (int j = 0; j < 128; j++) s += wf[k*128 + j] * wout[j];
    g_wfo[k] = s * (1.0f / 128.0f);   // 1/(sqrt(128)*sqrt(128))
}

// ---------------- per-edge features: bessel, attrs, env, Y -------------------
__global__ void k_feat(const float* __restrict__ ev, const float* __restrict__ attrs,
                       const int* __restrict__ src, const int* __restrict__ dst) {
    int e = blockIdx.x * blockDim.x + threadIdx.x;
    if (e >= NE) return;
    float x = ev[e*3+0], y = ev[e*3+1], z = ev[e*3+2];
    float d2 = x*x + y*y + z*z;
    float d  = sqrtf(d2 == 0.f ? 1.f : d2);
    const float SQ2 = 1.41421356237309515f;
    #pragma unroll
    for (int k = 0; k < 8; k++) {
        float b = SQ2 * sinf(3.14159265358979f * (float)(k+1) * d) / d;
        g_feat[e*40 + k] = (b - g_basis[k]) / g_basis[8 + k];
    }
    int s = src[e], t = dst[e];
    #pragma unroll
    for (int a = 0; a < 16; a++) {
        g_feat[e*40 + 8  + a] = attrs[s*16 + a];
        g_feat[e*40 + 24 + a] = attrs[t*16 + a];
    }
    float d6 = d2*d2*d2, d7 = d6*d, d8 = d7*d;
    g_env[e] = 1.0f - 28.0f*d6 + 48.0f*d7 - 21.0f*d8;
    float inv = 1.0f / d;
    float rx = x*inv, ry = y*inv, rz = z*inv;
    const float s3  = 1.7320508075688772f;
    const float s15 = 3.872983346207417f;
    const float s5  = 2.2360679774997896f;
    g_Y[e*9+0] = 1.0f;
    g_Y[e*9+1] = s3*rx;  g_Y[e*9+2] = s3*ry;  g_Y[e*9+3] = s3*rz;
    g_Y[e*9+4] = s15*rx*ry;
    g_Y[e*9+5] = s15*ry*rz;
    g_Y[e*9+6] = 0.5f*s5*(3.0f*rz*rz - 1.0f);
    g_Y[e*9+7] = s15*rx*rz;
    g_Y[e*9+8] = 0.5f*s15*(rx*rx - ry*ry);
}

// ---------------- CSR build ---------------------------------------------------
__global__ void k_count(const int* __restrict__ src) {
    int e = blockIdx.x * blockDim.x + threadIdx.x;
    if (e < NE) atomicAdd(&g_deg[src[e]], 1);
}
__global__ void k_scan() {
    __shared__ int partial[256];
    int t = threadIdx.x;
    const int CH = (NN + 255) / 256;     // 79
    int lo = t * CH, hi = min(lo + CH, NN);
    int s = 0;
    for (int i = lo; i < hi; i++) s += g_deg[i];
    partial[t] = s;
    __syncthreads();
    if (t == 0) {
        int run = 0;
        for (int i = 0; i < 256; i++) { int v = partial[i]; partial[i] = run; run += v; }
    }
    __syncthreads();
    int run = partial[t];
    for (int i = lo; i < hi; i++) {
        int dgr = g_deg[i];
        g_off[i] = run; g_cur[i] = run;
        run += dgr;
    }
    if (t == 255) g_off[NN] = run;
}
__global__ void k_fill(const int* __restrict__ src) {
    int e = blockIdx.x * blockDim.x + threadIdx.x;
    if (e >= NE) return;
    int pos = atomicAdd(&g_cur[src[e]], 1);
    g_eid[pos] = e;
}

// ---------------- aggregation: warp per node, lane = channel ------------------
__global__ void k_agg() {
    int n = blockIdx.x * (blockDim.x >> 5) + (threadIdx.x >> 5);
    int c = threadIdx.x & 31;
    if (n >= NN) return;
    int lo = g_off[n], hi = g_off[n+1];
    float acc[9];
    #pragma unroll
    for (int m = 0; m < 9; m++) acc[m] = 0.f;
    for (int k = lo; k < hi; k++) {
        int e = g_eid[k];
        float w = g_w2[e*32 + c];
        const float* ye = &g_Y[e*9];
        #pragma unroll
        for (int m = 0; m < 9; m++) acc[m] += w * ye[m];
    }
    float* o = &g_agg[n*288 + c*9];
    #pragma unroll
    for (int m = 0; m < 9; m++) o[m] = acc[m];
}

// ---------------- tiled GEMM: 64 edges per block, 256 threads ----------------
// Activations staged feature-major (row stride 68 -> float4-aligned), weights
// in smem. thread = (o, edge_group); all smem reads broadcast / conflict-free.
template<int IA, int IB, int O, int MODE>
__global__ void __launch_bounds__(256)
k_gemm(const float* __restrict__ A, const float* __restrict__ B,
       const float* __restrict__ W, float* __restrict__ out) {
    constexpr int I   = IA + IB;
    constexpr int T   = 64;
    constexpr int NT  = 256;
    constexpr int EPG = (T * O) / NT;  // edges per thread
    constexpr int LD  = T + 4;         // 68
    extern __shared__ float sm[];
    float* in_s = sm;             // I * LD
    float* W_s  = sm + I * LD;    // I * O

    int tid = threadIdx.x;
    int e0  = blockIdx.x * T;

    for (int i = tid; i < I * O; i += NT) W_s[i] = W[i];
    for (int i = tid; i < T * IA; i += NT) {
        int e = i / IA, f = i % IA;
        in_s[f * LD + e] = A[(size_t)(e0 + e) * IA + f];
    }
    if (IB > 0) {
        for (int i = tid; i < T * IB; i += NT) {
            int e = i / IB, f = i % IB;
            in_s[(IA + f) * LD + e] = B[(size_t)(e0 + e) * IB + f];
        }
    }
    __syncthreads();

    int o     = tid % O;
    int ebase = (tid / O) * EPG;

    float acc[EPG];
    #pragma unroll
    for (int j = 0; j < EPG; j++) acc[j] = 0.f;

    #pragma unroll 2
    for (int k = 0; k < I; k++) {
        float w = W_s[k * O + o];
        const float4* p = (const float4*)&in_s[k * LD + ebase];
        #pragma unroll
        for (int j4 = 0; j4 < EPG / 4; j4++) {
            float4 v = p[j4];
            acc[4*j4+0] += v.x * w;
            acc[4*j4+1] += v.y * w;
            acc[4*j4+2] += v.z * w;
            acc[4*j4+3] += v.w * w;
        }
    }

    float scale = 1.0f / sqrtf((float)I);
    const float rs = 0.8944271909999159f;  // 1/sqrt(1.25)
    #pragma unroll
    for (int j = 0; j < EPG; j++) {
        int e = e0 + ebase + j;
        float v = acc[j] * scale;
        if (MODE == M_SILU)  v = v / (1.0f + expf(-v));
        if (MODE == M_ENV)   v = v * g_env[e];
        if (MODE == M_RESID) v = (g_x[(size_t)e*128 + o] + 0.5f * g_env[e] * v) * rs;
        out[(size_t)e * O + o] = v;
    }
}

// ---------------- V1 init: V1 = V0 (x) Y1 -------------------------------------
__global__ void k_makev1() {
    int i = blockIdx.x * blockDim.x + threadIdx.x;
    if (i >= NE * 96) return;
    int e = i / 96, r = i % 96, c = r / 3, t = r % 3;
    g_V1a[i] = g_V0[e*32 + c] * g_Y[e*9 + 1 + t];
}

// ---------------- per-layer: build s (scalars) and V1new (vector mixing) -----
template<int L1>
__global__ void k_pre(const int* __restrict__ src, const float* __restrict__ lin,
                      const float* __restrict__ V1in, float* __restrict__ V1out) {
    constexpr int M  = L1 ? 96 : 64;
    constexpr int LD = 36;
    extern __shared__ float sm[];
    float* Vm    = sm;            // 3*M*LD
    float* lin_s = sm + 3*M*LD;   // M*32

    int tid = threadIdx.x;
    int e0  = blockIdx.x * 32;
    for (int i = tid; i < M * 32; i += 128) lin_s[i] = lin[i];

    int c = tid & 31, eg = tid >> 5;
    const float s15h = 1.9364916731037085f;  // 0.5*sqrt(15)
    const float s5h  = 1.1180339887498949f;  // 0.5*sqrt(5)
    const float s5   = 2.2360679774997896f;
    const float itp  = 0.28284271247461906f; // 1/sqrt(12.5)
    const float is3  = 0.5773502691896258f;  // 1/sqrt(3)

    for (int j = 0; j < 8; j++) {
        int el = eg * 8 + j;
        int e  = e0 + el;
        int sn = src[e];
        const float* ag = &g_agg[sn * 288 + c * 9];
        float A0  = ag[0]*0.25f;
        float A1x = ag[1]*0.25f, A1y = ag[2]*0.25f, A1z = ag[3]*0.25f;
        float axy = ag[4]*0.25f, ayz = ag[5]*0.25f, az2 = ag[6]*0.25f;
        float axz = ag[7]*0.25f, ax2 = ag[8]*0.25f;
        float vx = V1in[e*96 + c*3 + 0];
        float vy = V1in[e*96 + c*3 + 1];
        float vz = V1in[e*96 + c*3 + 2];
        float sc1 = (A1x*vx + A1y*vy + A1z*vz) * is3;
        if (L1) {
            float v0 = g_V0[e*32 + c];
            g_s[e*64 + c*2 + 0] = A0 * v0;
            g_s[e*64 + c*2 + 1] = sc1;
            Vm[(0*M + 32 + c)*LD + el] = A1x * v0;
            Vm[(1*M + 32 + c)*LD + el] = A1y * v0;
            Vm[(2*M + 32 + c)*LD + el] = A1z * v0;
        } else {
            g_s[e*32 + c] = sc1;
        }
        Vm[(0*M + c)*LD + el] = A0 * vx;
        Vm[(1*M + c)*LD + el] = A0 * vy;
        Vm[(2*M + c)*LD + el] = A0 * vz;
        float mxx = -s5h*az2 + s15h*ax2;
        float myy = -s5h*az2 - s15h*ax2;
        float mzz =  s5 * az2;
        float mxy = s15h*axy, mxz = s15h*axz, myz = s15h*ayz;
        int toff = L1 ? 64 : 32;
        Vm[(0*M + toff + c)*LD + el] = (mxx*vx + mxy*vy + mxz*vz) * itp;
        Vm[(1*M + toff + c)*LD + el] = (mxy*vx + myy*vy + myz*vz) * itp;
        Vm[(2*M + toff + c)*LD + el] = (mxz*vx + myz*vy + mzz*vz) * itp;
    }
    __syncthreads();

    float acc[3][8];
    #pragma unroll
    for (int t = 0; t < 3; t++)
        #pragma unroll
        for (int j = 0; j < 8; j++) acc[t][j] = 0.f;

    int ebase = eg * 8;
    #pragma unroll 2
    for (int m = 0; m < M; m++) {
        float l = lin_s[m*32 + c];
        #pragma unroll
        for (int t = 0; t < 3; t++) {
            const float4* p = (const float4*)&Vm[(t*M + m)*LD + ebase];
            float4 a = p[0], b = p[1];
            acc[t][0] += a.x*l; acc[t][1] += a.y*l; acc[t][2] += a.z*l; acc[t][3] += a.w*l;
            acc[t][4] += b.x*l; acc[t][5] += b.y*l; acc[t][6] += b.z*l; acc[t][7] += b.w*l;
        }
    }
    float sc = 1.0f / sqrtf((float)M);
    for (int j = 0; j < 8; j++) {
        int e = e0 + ebase + j;
        #pragma unroll
        for (int t = 0; t < 3; t++)
            V1out[e*96 + c*3 + t] = acc[t][j] * sc;
    }
}

// ---------------- final: out = x . wfo ---------------------------------------
__global__ void k_final(float* __restrict__ out) {
    int gt = blockIdx.x * blockDim.x + threadIdx.x;
    int e  = gt >> 5;
    int lane = threadIdx.x & 31;
    if (e >= NE) return;
    const float* xr = &g_x[(size_t)e * 128];
    float s = xr[lane]      * g_wfo[lane]
            + xr[lane + 32] * g_wfo[lane + 32]
            + xr[lane + 64] * g_wfo[lane + 64]
            + xr[lane + 96] * g_wfo[lane + 96];
    #pragma unroll
    for (int off = 16; off; off >>= 1) s += __shfl_down_sync(0xffffffffu, s, off);
    if (lane == 0) out[e] = s;
}

// ---------------- host side ---------------------------------------------------
template<int IA, int IB, int O, int MODE>
static void launch_gemm(const float* A, const float* B, const float* W, float* out) {
    constexpr int I = IA + IB;
    size_t smem = (size_t)(I * 68 + I * O) * sizeof(float);
    cudaFuncSetAttribute(k_gemm<IA, IB, O, MODE>,
                         cudaFuncAttributeMaxDynamicSharedMemorySize, (int)smem);
    k_gemm<IA, IB, O, MODE><<<NE / 64, 256, smem>>>(A, B, W, out);
}

extern "C" void kernel_launch(void* const* d_in, const int* in_sizes, int n_in,
                              void* d_out, int out_size) {
    const float* node_attrs = (const float*)d_in[0];
    const float* ev         = (const float*)d_in[1];
    const float* w_emb0     = (const float*)d_in[2];
    const float* w_emb1     = (const float*)d_in[3];
    const float* w_emb2     = (const float*)d_in[4];
    const float* w_emb3     = (const float*)d_in[5];
    const float* w_w0       = (const float*)d_in[6];
    const float* w_w[3]  = { (const float*)d_in[7],  (const float*)d_in[12], (const float*)d_in[17] };
    const float* lat0[3] = { (const float*)d_in[8],  (const float*)d_in[13], (const float*)d_in[18] };
    const float* lat1[3] = { (const float*)d_in[9],  (const float*)d_in[14], (const float*)d_in[19] };
    const float* lat2[3] = { (const float*)d_in[10], (const float*)d_in[15], (const float*)d_in[20] };
    const float* lin[3]  = { (const float*)d_in[11], (const float*)d_in[16], (const float*)d_in[21] };
    const float* w_f   = (const float*)d_in[22];
    const float* w_out = (const float*)d_in[23];
    const int*   src   = (const int*)d_in[24];
    const int*   dst   = (const int*)d_in[25];
    float* out = (float*)d_out;

    float *p_feat, *p_x, *p_t1, *p_t2, *p_V0, *p_V1a, *p_V1b, *p_s, *p_w2;
    int *p_deg;
    cudaGetSymbolAddress((void**)&p_feat, g_feat);
    cudaGetSymbolAddress((void**)&p_x,   g_x);
    cudaGetSymbolAddress((void**)&p_t1,  g_t1);
    cudaGetSymbolAddress((void**)&p_t2,  g_t2);
    cudaGetSymbolAddress((void**)&p_V0,  g_V0);
    cudaGetSymbolAddress((void**)&p_V1a, g_V1a);
    cudaGetSymbolAddress((void**)&p_V1b, g_V1b);
    cudaGetSymbolAddress((void**)&p_s,   g_s);
    cudaGetSymbolAddress((void**)&p_w2,  g_w2);
    cudaGetSymbolAddress((void**)&p_deg, g_deg);

    {
        size_t sm1 = (size_t)(3*96*36 + 96*32) * sizeof(float);
        size_t sm0 = (size_t)(3*64*36 + 64*32) * sizeof(float);
        cudaFuncSetAttribute(k_pre<1>, cudaFuncAttributeMaxDynamicSharedMemorySize, (int)sm1);
        cudaFuncSetAttribute(k_pre<0>, cudaFuncAttributeMaxDynamicSharedMemorySize, (int)sm0);
    }

    k_init<<<1, 256>>>();
    k_wfo<<<1, 128>>>(w_f, w_out);
    k_feat<<<(NE + 255) / 256, 256>>>(ev, node_attrs, src, dst);

    // CSR build (graph fixed across layers)
    cudaMemsetAsync(p_deg, 0, NN * sizeof(int));
    k_count<<<(NE + 255) / 256, 256>>>(src);
    k_scan<<<1, 256>>>();
    k_fill<<<(NE + 255) / 256, 256>>>(src);

    // embedding MLP: 40 -> 16 -> 32 -> 64 -> 128 (silu x3, none) then *env
    launch_gemm<40, 0, 16,  M_SILU>(p_feat, nullptr, w_emb0, p_t1);
    launch_gemm<16, 0, 32,  M_SILU>(p_t1,   nullptr, w_emb1, p_t2);
    launch_gemm<32, 0, 64,  M_SILU>(p_t2,   nullptr, w_emb2, p_t1);
    launch_gemm<64, 0, 128, M_ENV >(p_t1,   nullptr, w_emb3, p_x);

    // V0 = x @ w_w0 / sqrt(128);  V1 = V0 (x) Y1
    launch_gemm<128, 0, 32, M_NONE>(p_x, nullptr, w_w0, p_V0);
    k_makev1<<<(NE * 96 + 255) / 256, 256>>>();

    float* vin  = p_V1a;
    float* vout = p_V1b;
    for (int l = 0; l < 3; l++) {
        launch_gemm<128, 0, 32, M_NONE>(p_x, nullptr, w_w[l], p_w2);
        k_agg<<<(NN + 7) / 8, 256>>>();
        if (l == 0) {
            size_t sm1 = (size_t)(3*96*36 + 96*32) * sizeof(float);
            k_pre<1><<<NE / 32, 128, sm1>>>(src, lin[l], vin, vout);
            launch_gemm<128, 64, 128, M_SILU>(p_x, p_s, lat0[l], p_t1);
        } else {
            size_t sm0 = (size_t)(3*64*36 + 64*32) * sizeof(float);
            k_pre<0><<<NE / 32, 128, sm0>>>(src, lin[l], vin, vout);
            launch_gemm<128, 32, 128, M_SILU>(p_x, p_s, lat0[l], p_t1);
        }
        launch_gemm<128, 0, 128, M_SILU >(p_t1, nullptr, lat1[l], p_t2);
        launch_gemm<128, 0, 128, M_RESID>(p_t2, nullptr, lat2[l], p_x);
        float* tmp = vin; vin = vout; vout = tmp;
    }

    k_final<<<(NE * 32 + 255) / 256, 256>>>(out);
    (void)in_sizes; (void)n_in; (void)out_size; (void)dst;
}

// round 4
// speedup vs baseline: 1.0581x; 1.0581x over previous
#include <cuda_runtime.h>
#include <math.h>

#define NN 20000
#define NE 320000
#define PI_D 3.14159265358979323846

enum { M_NONE=0, M_SILU=1, M_ENV=2, M_RESID=3 };

// ---------------- scratch (static device globals; no allocation) -------------
__device__ float g_basis[16];
__device__ float g_wfo[128];
__device__ float g_feat[NE*40];
__device__ float g_x  [NE*128];
__device__ float g_t1 [NE*128];
__device__ float g_t2 [NE*128];
__device__ float g_env[NE];
__device__ float g_Y  [NE*9];
__device__ float g_V0 [NE*32];
__device__ float g_V1a[NE*96];
__device__ float g_V1b[NE*96];
__device__ float g_s  [NE*64];
__device__ float g_w2 [NE*32];
__device__ float g_agg[NN*288];
__device__ int   g_deg[NN];
__device__ int   g_off[NN+1];
__device__ int   g_cur[NN];
__device__ int   g_eid[NE];

// ---------------- packed f32x2 helpers ---------------------------------------
__device__ __forceinline__ void ffma2(unsigned long long& d,
                                      unsigned long long a,
                                      unsigned long long b) {
    asm("fma.rn.f32x2 %0, %1, %2, %0;" : "+l"(d) : "l"(a), "l"(b));
}
__device__ __forceinline__ unsigned long long pack2(float v) {
    unsigned u = __float_as_uint(v);
    return (unsigned long long)u * 0x100000001ULL;
}

// ---------------- basis constants via trapz (matches numpy) ------------------
__global__ void k_init() {
    int k    = threadIdx.x >> 5;
    int lane = threadIdx.x & 31;
    double kk = (double)(k + 1);
    double h  = (1.0 - 1e-9) / 999.0;
    double s = 0.0;
    for (int i = lane; i < 1000; i += 32) {
        double r = 1e-9 + h * (double)i;
        s += sqrt(2.0) * sin(PI_D * kk * r) / r;
    }
    #pragma unroll
    for (int off = 16; off; off >>= 1) s += __shfl_xor_sync(0xffffffffu, s, off);
    double r0 = 1e-9, r9 = 1e-9 + h * 999.0;
    double b0 = sqrt(2.0) * sin(PI_D * kk * r0) / r0;
    double b9 = sqrt(2.0) * sin(PI_D * kk * r9) / r9;
    double mu = h * (s - 0.5 * (b0 + b9));
    double q = 0.0;
    for (int i = lane; i < 1000; i += 32) {
        double r = 1e-9 + h * (double)i;
        double b = sqrt(2.0) * sin(PI_D * kk * r) / r;
        double dd = b - mu;
        q += dd * dd;
    }
    #pragma unroll
    for (int off = 16; off; off >>= 1) q += __shfl_xor_sync(0xffffffffu, q, off);
    double q0 = (b0 - mu) * (b0 - mu), q9 = (b9 - mu) * (b9 - mu);
    double s2 = h * (q - 0.5 * (q0 + q9));
    if (lane == 0) {
        g_basis[k]     = (float)mu;
        g_basis[8 + k] = (float)sqrt(s2);
    }
}

__global__ void k_wfo(const float* __restrict__ wf, const float* __restrict__ wout) {
    int k = threadIdx.x;
    float s = 0.f;
    for (int j = 0; j < 128; j++) s += wf[k*128 + j] * wout[j];
    g_wfo[k] = s * (1.0f / 128.0f);
}

// ---------------- per-edge features ------------------------------------------
__global__ void k_feat(const float* __restrict__ ev, const float* __restrict__ attrs,
                       const int* __restrict__ src, const int* __restrict__ dst) {
    int e = blockIdx.x * blockDim.x + threadIdx.x;
    if (e >= NE) return;
    float x = ev[e*3+0], y = ev[e*3+1], z = ev[e*3+2];
    float d2 = x*x + y*y + z*z;
    float d  = sqrtf(d2 == 0.f ? 1.f : d2);
    const float SQ2 = 1.41421356237309515f;
    #pragma unroll
    for (int k = 0; k < 8; k++) {
        float b = SQ2 * sinf(3.14159265358979f * (float)(k+1) * d) / d;
        g_feat[e*40 + k] = (b - g_basis[k]) / g_basis[8 + k];
    }
    int s = src[e], t = dst[e];
    // attrs rows are 16 floats (64B) -> 4x float4 per row; g_feat rows are 40
    // floats so offsets 8 and 24 are float4-aligned.
    {
        const float4* pa = (const float4*)&attrs[s*16];
        const float4* pb = (const float4*)&attrs[t*16];
        float4* oa = (float4*)&g_feat[e*40 + 8];
        float4* ob = (float4*)&g_feat[e*40 + 24];
        #pragma unroll
        for (int q = 0; q < 4; q++) oa[q] = pa[q];
        #pragma unroll
        for (int q = 0; q < 4; q++) ob[q] = pb[q];
    }
    float d6 = d2*d2*d2, d7 = d6*d, d8 = d7*d;
    g_env[e] = 1.0f - 28.0f*d6 + 48.0f*d7 - 21.0f*d8;
    float inv = 1.0f / d;
    float rx = x*inv, ry = y*inv, rz = z*inv;
    const float s3  = 1.7320508075688772f;
    const float s15 = 3.872983346207417f;
    const float s5  = 2.2360679774997896f;
    g_Y[e*9+0] = 1.0f;
    g_Y[e*9+1] = s3*rx;  g_Y[e*9+2] = s3*ry;  g_Y[e*9+3] = s3*rz;
    g_Y[e*9+4] = s15*rx*ry;
    g_Y[e*9+5] = s15*ry*rz;
    g_Y[e*9+6] = 0.5f*s5*(3.0f*rz*rz - 1.0f);
    g_Y[e*9+7] = s15*rx*rz;
    g_Y[e*9+8] = 0.5f*s15*(rx*rx - ry*ry);
}

// ---------------- CSR build ---------------------------------------------------
__global__ void k_count(const int* __restrict__ src) {
    int e = blockIdx.x * blockDim.x + threadIdx.x;
    if (e < NE) atomicAdd(&g_deg[src[e]], 1);
}
__global__ void k_scan() {
    __shared__ int partial[256];
    int t = threadIdx.x;
    const int CH = (NN + 255) / 256;
    int lo = t * CH, hi = min(lo + CH, NN);
    int s = 0;
    for (int i = lo; i < hi; i++) s += g_deg[i];
    partial[t] = s;
    __syncthreads();
    if (t == 0) {
        int run = 0;
        for (int i = 0; i < 256; i++) { int v = partial[i]; partial[i] = run; run += v; }
    }
    __syncthreads();
    int run = partial[t];
    for (int i = lo; i < hi; i++) {
        int dgr = g_deg[i];
        g_off[i] = run; g_cur[i] = run;
        run += dgr;
    }
    if (t == 255) g_off[NN] = run;
}
__global__ void k_fill(const int* __restrict__ src) {
    int e = blockIdx.x * blockDim.x + threadIdx.x;
    if (e >= NE) return;
    int pos = atomicAdd(&g_cur[src[e]], 1);
    g_eid[pos] = e;
}

// ---------------- aggregation: warp per node, lane = channel ------------------
__global__ void k_agg() {
    int n = blockIdx.x * (blockDim.x >> 5) + (threadIdx.x >> 5);
    int c = threadIdx.x & 31;
    if (n >= NN) return;
    int lo = g_off[n], hi = g_off[n+1];
    float acc[9];
    #pragma unroll
    for (int m = 0; m < 9; m++) acc[m] = 0.f;
    for (int k = lo; k < hi; k++) {
        int e = __ldg(&g_eid[k]);
        float w = __ldg(&g_w2[e*32 + c]);
        const float* ye = &g_Y[e*9];
        #pragma unroll
        for (int m = 0; m < 9; m++) acc[m] += w * __ldg(&ye[m]);
    }
    float* o = &g_agg[n*288 + c*9];
    #pragma unroll
    for (int m = 0; m < 9; m++) o[m] = acc[m];
}

// ---------------- tiled GEMM: 64 edges/block, 256 threads, f32x2 FMA ---------
template<int IA, int IB, int O, int MODE>
__global__ void __launch_bounds__(256)
k_gemm(const float* __restrict__ A, const float* __restrict__ B,
       const float* __restrict__ W, float* __restrict__ out) {
    constexpr int I   = IA + IB;
    constexpr int T   = 64;
    constexpr int NT  = 256;
    constexpr int EPG = (T * O) / NT;   // edges per thread (4..32, mult of 4)
    constexpr int LD  = T + 4;          // 68 (k*LD*4 stays 16B aligned)
    extern __shared__ float sm[];
    float* in_s = sm;             // I * LD
    float* W_s  = sm + I * LD;    // I * O

    int tid = threadIdx.x;
    int e0  = blockIdx.x * T;

    for (int i = tid; i < I * O; i += NT) W_s[i] = W[i];
    for (int i = tid; i < T * IA; i += NT) {
        int e = i / IA, f = i % IA;
        in_s[f * LD + e] = A[(size_t)(e0 + e) * IA + f];
    }
    if (IB > 0) {
        for (int i = tid; i < T * IB; i += NT) {
            int e = i / IB, f = i % IB;
            in_s[(IA + f) * LD + e] = B[(size_t)(e0 + e) * IB + f];
        }
    }
    __syncthreads();

    int o     = tid % O;
    int ebase = (tid / O) * EPG;

    unsigned long long acc2[EPG/2];
    #pragma unroll
    for (int j = 0; j < EPG/2; j++) acc2[j] = 0ULL;

    #pragma unroll 2
    for (int k = 0; k < I; k++) {
        unsigned long long wp = pack2(W_s[k * O + o]);
        const ulonglong2* p = (const ulonglong2*)&in_s[k * LD + ebase];
        #pragma unroll
        for (int j4 = 0; j4 < EPG / 4; j4++) {
            ulonglong2 v = p[j4];        // one LDS.128 (broadcast across warp)
            ffma2(acc2[2*j4+0], v.x, wp);
            ffma2(acc2[2*j4+1], v.y, wp);
        }
    }

    float scale = 1.0f / sqrtf((float)I);
    const float rs = 0.8944271909999159f;  // 1/sqrt(1.25)
    #pragma unroll
    for (int j = 0; j < EPG/2; j++) {
        float2 f2 = *(float2*)&acc2[j];
        #pragma unroll
        for (int h = 0; h < 2; h++) {
            int e = e0 + ebase + 2*j + h;
            float v = (h ? f2.y : f2.x) * scale;
            if (MODE == M_SILU)  v = v / (1.0f + __expf(-v));
            if (MODE == M_ENV)   v = v * g_env[e];
            if (MODE == M_RESID) v = (g_x[(size_t)e*128 + o] + 0.5f * g_env[e] * v) * rs;
            out[(size_t)e * O + o] = v;
        }
    }
}

// ---------------- per-layer: scalars s + vector mixing (f32x2) ---------------
// L1: V1in is implicit (V0 x Y1), computed on the fly.
template<int L1>
__global__ void k_pre(const int* __restrict__ src, const float* __restrict__ lin,
                      const float* __restrict__ V1in, float* __restrict__ V1out) {
    constexpr int M  = L1 ? 96 : 64;
    constexpr int LD = 36;
    extern __shared__ float sm[];
    float* Vm    = sm;            // 3*M*LD
    float* lin_s = sm + 3*M*LD;   // M*32

    int tid = threadIdx.x;
    int e0  = blockIdx.x * 32;
    for (int i = tid; i < M * 32; i += 128) lin_s[i] = lin[i];

    int c = tid & 31, eg = tid >> 5;
    const float s15h = 1.9364916731037085f;
    const float s5h  = 1.1180339887498949f;
    const float s5   = 2.2360679774997896f;
    const float itp  = 0.28284271247461906f; // 1/sqrt(12.5)
    const float is3  = 0.5773502691896258f;  // 1/sqrt(3)

    for (int j = 0; j < 8; j++) {
        int el = eg * 8 + j;
        int e  = e0 + el;
        int sn = src[e];
        const float* ag = &g_agg[sn * 288 + c * 9];
        float A0  = ag[0]*0.25f;
        float A1x = ag[1]*0.25f, A1y = ag[2]*0.25f, A1z = ag[3]*0.25f;
        float axy = ag[4]*0.25f, ayz = ag[5]*0.25f, az2 = ag[6]*0.25f;
        float axz = ag[7]*0.25f, ax2 = ag[8]*0.25f;
        float vx, vy, vz, v0 = 0.f;
        if (L1) {
            v0 = g_V0[e*32 + c];
            vx = v0 * g_Y[e*9+1];
            vy = v0 * g_Y[e*9+2];
            vz = v0 * g_Y[e*9+3];
        } else {
            vx = V1in[e*96 + c*3 + 0];
            vy = V1in[e*96 + c*3 + 1];
            vz = V1in[e*96 + c*3 + 2];
        }
        float sc1 = (A1x*vx + A1y*vy + A1z*vz) * is3;
        if (L1) {
            g_s[e*64 + c*2 + 0] = A0 * v0;
            g_s[e*64 + c*2 + 1] = sc1;
            Vm[(0*M + 32 + c)*LD + el] = A1x * v0;
            Vm[(1*M + 32 + c)*LD + el] = A1y * v0;
            Vm[(2*M + 32 + c)*LD + el] = A1z * v0;
        } else {
            g_s[e*32 + c] = sc1;
        }
        Vm[(0*M + c)*LD + el] = A0 * vx;
        Vm[(1*M + c)*LD + el] = A0 * vy;
        Vm[(2*M + c)*LD + el] = A0 * vz;
        float mxx = -s5h*az2 + s15h*ax2;
        float myy = -s5h*az2 - s15h*ax2;
        float mzz =  s5 * az2;
        float mxy = s15h*axy, mxz = s15h*axz, myz = s15h*ayz;
        int toff = L1 ? 64 : 32;
        Vm[(0*M + toff + c)*LD + el] = (mxx*vx + mxy*vy + mxz*vz) * itp;
        Vm[(1*M + toff + c)*LD + el] = (mxy*vx + myy*vy + myz*vz) * itp;
        Vm[(2*M + toff + c)*LD + el] = (mxz*vx + myz*vy + mzz*vz) * itp;
    }
    __syncthreads();

    unsigned long long acc2[3][4];
    #pragma unroll
    for (int t = 0; t < 3; t++)
        #pragma unroll
        for (int j = 0; j < 4; j++) acc2[t][j] = 0ULL;

    int ebase = eg * 8;
    #pragma unroll 2
    for (int m = 0; m < M; m++) {
        unsigned long long lp = pack2(lin_s[m*32 + c]);
        #pragma unroll
        for (int t = 0; t < 3; t++) {
            const ulonglong2* p = (const ulonglong2*)&Vm[(t*M + m)*LD + ebase];
            ulonglong2 a = p[0], b = p[1];
            ffma2(acc2[t][0], a.x, lp);
            ffma2(acc2[t][1], a.y, lp);
            ffma2(acc2[t][2], b.x, lp);
            ffma2(acc2[t][3], b.y, lp);
        }
    }
    float sc = 1.0f / sqrtf((float)M);
    #pragma unroll
    for (int j = 0; j < 4; j++) {
        #pragma unroll
        for (int t = 0; t < 3; t++) {
            float2 f2 = *(float2*)&acc2[t][j];
            int ea = e0 + ebase + 2*j, eb = ea + 1;
            V1out[ea*96 + c*3 + t] = f2.x * sc;
            V1out[eb*96 + c*3 + t] = f2.y * sc;
        }
    }
}

// ---------------- final: out = x . wfo ---------------------------------------
__global__ void k_final(float* __restrict__ out) {
    int gt = blockIdx.x * blockDim.x + threadIdx.x;
    int e  = gt >> 5;
    int lane = threadIdx.x & 31;
    if (e >= NE) return;
    const float* xr = &g_x[(size_t)e * 128];
    float s = xr[lane]      * g_wfo[lane]
            + xr[lane + 32] * g_wfo[lane + 32]
            + xr[lane + 64] * g_wfo[lane + 64]
            + xr[lane + 96] * g_wfo[lane + 96];
    #pragma unroll
    for (int off = 16; off; off >>= 1) s += __shfl_down_sync(0xffffffffu, s, off);
    if (lane == 0) out[e] = s;
}

// ---------------- host side ---------------------------------------------------
template<int IA, int IB, int O, int MODE>
static void launch_gemm(const float* A, const float* B, const float* W, float* out) {
    constexpr int I = IA + IB;
    size_t smem = (size_t)(I * 68 + I * O) * sizeof(float);
    cudaFuncSetAttribute(k_gemm<IA, IB, O, MODE>,
                         cudaFuncAttributeMaxDynamicSharedMemorySize, (int)smem);
    k_gemm<IA, IB, O, MODE><<<NE / 64, 256, smem>>>(A, B, W, out);
}

extern "C" void kernel_launch(void* const* d_in, const int* in_sizes, int n_in,
                              void* d_out, int out_size) {
    const float* node_attrs = (const float*)d_in[0];
    const float* ev         = (const float*)d_in[1];
    const float* w_emb0     = (const float*)d_in[2];
    const float* w_emb1     = (const float*)d_in[3];
    const float* w_emb2     = (const float*)d_in[4];
    const float* w_emb3     = (const float*)d_in[5];
    const float* w_w0       = (const float*)d_in[6];
    const float* w_w[3]  = { (const float*)d_in[7],  (const float*)d_in[12], (const float*)d_in[17] };
    const float* lat0[3] = { (const float*)d_in[8],  (const float*)d_in[13], (const float*)d_in[18] };
    const float* lat1[3] = { (const float*)d_in[9],  (const float*)d_in[14], (const float*)d_in[19] };
    const float* lat2[3] = { (const float*)d_in[10], (const float*)d_in[15], (const float*)d_in[20] };
    const float* lin[3]  = { (const float*)d_in[11], (const float*)d_in[16], (const float*)d_in[21] };
    const float* w_f   = (const float*)d_in[22];
    const float* w_out = (const float*)d_in[23];
    const int*   src   = (const int*)d_in[24];
    const int*   dst   = (const int*)d_in[25];
    float* out = (float*)d_out;

    float *p_feat, *p_x, *p_t1, *p_t2, *p_V0, *p_V1a, *p_V1b, *p_s, *p_w2;
    int *p_deg;
    cudaGetSymbolAddress((void**)&p_feat, g_feat);
    cudaGetSymbolAddress((void**)&p_x,   g_x);
    cudaGetSymbolAddress((void**)&p_t1,  g_t1);
    cudaGetSymbolAddress((void**)&p_t2,  g_t2);
    cudaGetSymbolAddress((void**)&p_V0,  g_V0);
    cudaGetSymbolAddress((void**)&p_V1a, g_V1a);
    cudaGetSymbolAddress((void**)&p_V1b, g_V1b);
    cudaGetSymbolAddress((void**)&p_s,   g_s);
    cudaGetSymbolAddress((void**)&p_w2,  g_w2);
    cudaGetSymbolAddress((void**)&p_deg, g_deg);

    {
        size_t sm1 = (size_t)(3*96*36 + 96*32) * sizeof(float);
        size_t sm0 = (size_t)(3*64*36 + 64*32) * sizeof(float);
        cudaFuncSetAttribute(k_pre<1>, cudaFuncAttributeMaxDynamicSharedMemorySize, (int)sm1);
        cudaFuncSetAttribute(k_pre<0>, cudaFuncAttributeMaxDynamicSharedMemorySize, (int)sm0);
    }

    k_init<<<1, 256>>>();
    k_wfo<<<1, 128>>>(w_f, w_out);
    k_feat<<<(NE + 255) / 256, 256>>>(ev, node_attrs, src, dst);

    cudaMemsetAsync(p_deg, 0, NN * sizeof(int));
    k_count<<<(NE + 255) / 256, 256>>>(src);
    k_scan<<<1, 256>>>();
    k_fill<<<(NE + 255) / 256, 256>>>(src);

    launch_gemm<40, 0, 16,  M_SILU>(p_feat, nullptr, w_emb0, p_t1);
    launch_gemm<16, 0, 32,  M_SILU>(p_t1,   nullptr, w_emb1, p_t2);
    launch_gemm<32, 0, 64,  M_SILU>(p_t2,   nullptr, w_emb2, p_t1);
    launch_gemm<64, 0, 128, M_ENV >(p_t1,   nullptr, w_emb3, p_x);

    launch_gemm<128, 0, 32, M_NONE>(p_x, nullptr, w_w0, p_V0);

    float* vin  = p_V1a;
    float* vout = p_V1b;
    for (int l = 0; l < 3; l++) {
        launch_gemm<128, 0, 32, M_NONE>(p_x, nullptr, w_w[l], p_w2);
        k_agg<<<(NN + 7) / 8, 256>>>();
        if (l == 0) {
            size_t sm1 = (size_t)(3*96*36 + 96*32) * sizeof(float);
            k_pre<1><<<NE / 32, 128, sm1>>>(src, lin[l], vin, vout);
            launch_gemm<128, 64, 128, M_SILU>(p_x, p_s, lat0[l], p_t1);
        } else {
            size_t sm0 = (size_t)(3*64*36 + 64*32) * sizeof(float);
            k_pre<0><<<NE / 32, 128, sm0>>>(src, lin[l], vin, vout);
            launch_gemm<128, 32, 128, M_SILU>(p_x, p_s, lat0[l], p_t1);
        }
        launch_gemm<128, 0, 128, M_SILU >(p_t1, nullptr, lat1[l], p_t2);
        launch_gemm<128, 0, 128, M_RESID>(p_t2, nullptr, lat2[l], p_x);
        float* tmp = vin; vin = vout; vout = tmp;
    }

    k_final<<<(NE * 32 + 255) / 256, 256>>>(out);
    (void)in_sizes; (void)n_in; (void)out_size; (void)dst;
}